// round 17
// baseline (speedup 1.0000x reference)
#include <cuda_runtime.h>
#include <math.h>

#define DIM 192
#define NB 12
#define THREADS 128
#define FULLM 0xffffffffu
#define NEG_INF (-3.402823466e+38f)
#define POS_INF (3.402823466e+38f)

// f32 exchange: float2 z-pairs; element (col c, y, zpair j) at j*256 + c*16 + y
#define F2N 2048

// accumulators: [0]=sum(p*g) [1]=sum(p*p) [2]=sum(g*g) [3]=loss_cl
__device__ double g_acc[4] = {0.0, 0.0, 0.0, 0.0};
__device__ unsigned g_count = 0;

__device__ __forceinline__ float warp_sum(float v) {
#pragma unroll
    for (int o = 16; o; o >>= 1) v += __shfl_xor_sync(FULLM, v, o);
    return v;
}

// ---------------------------------------------------------------------------
// Thread (xp, y) owns TWO x-adjacent 16-z columns xA=2xp, xB=2xp+1.
//   x inner  : registers.  outer x / y+-1 (erode): published smem, LDS.64.
//   y (dilate xz-max) : segmented shfl width 16 (self-clamp = identity).
// gt binary: BOTH column masks packed in one 32-bit word (A: bits 0-15,
// B: bits 16-31); erode=AND, dilate=OR with boundary-mask fixups; exact.
// Ring f0->f1->f2; erode writes next level straight into the next buffer.
// ---------------------------------------------------------------------------

// in-place erode of both columns + store to write-buffer. All cross-thread
// taps (outer-x, y+-1) read from the published level rb. Shuffle-free.
__device__ __forceinline__ void erode_store(float (&a)[16], float (&b)[16],
                                            const float2* __restrict__ rb,
                                            float2* __restrict__ wb,
                                            int t2a, int t2b, int tl, int tr,
                                            int ayu, int ayd, bool lv, bool rv) {
    float belowA = POS_INF, belowB = POS_INF;
#pragma unroll
    for (int j = 0; j < 8; j++) {
        const int o = j * 256;
        float2 L  = rb[o + tl];
        float2 R  = rb[o + tr];
        float2 Au = rb[o + ayu],      Ad = rb[o + ayd];
        float2 Bu = rb[o + ayu + 16], Bd = rb[o + ayd + 16];
        float2 oA, oB;
        {   // k = 2j (k+1 always valid)
            const int k = 2 * j;
            float olda = a[k], oldb = b[k];
            float ma = fminf(fminf(olda, belowA), a[k + 1]);
            ma = fminf(ma, oldb);
            if (lv) ma = fminf(ma, L.x);
            ma = fminf(fminf(ma, Au.x), Ad.x);
            float mb = fminf(fminf(oldb, belowB), b[k + 1]);
            mb = fminf(mb, olda);
            if (rv) mb = fminf(mb, R.x);
            mb = fminf(fminf(mb, Bu.x), Bd.x);
            belowA = olda; belowB = oldb;
            a[k] = ma; b[k] = mb; oA.x = ma; oB.x = mb;
        }
        {   // k = 2j+1
            const int k = 2 * j + 1;
            float olda = a[k], oldb = b[k];
            float ma = fminf(olda, belowA);
            if (k < 15) ma = fminf(ma, a[k + 1]);
            ma = fminf(ma, oldb);
            if (lv) ma = fminf(ma, L.y);
            ma = fminf(fminf(ma, Au.y), Ad.y);
            float mb = fminf(oldb, belowB);
            if (k < 15) mb = fminf(mb, b[k + 1]);
            mb = fminf(mb, olda);
            if (rv) mb = fminf(mb, R.y);
            mb = fminf(fminf(mb, Bu.y), Bd.y);
            belowA = olda; belowB = oldb;
            a[k] = ma; b[k] = mb; oA.y = ma; oB.y = mb;
        }
        wb[o + t2a] = oA;
        wb[o + t2b] = oB;
    }
}

// dilate (3x3x3 max, -inf pad) fused with skel init/update.
template <bool FIRST>
__device__ __forceinline__ void dilate_upd(const float (&a)[16], const float (&b)[16],
                                           float (&sA)[16], float (&sB)[16],
                                           const float2* __restrict__ eb,
                                           const float2* __restrict__ pb,
                                           int t2a, int t2b, int tl, int tr,
                                           bool lv, bool rv) {
    float2 Lc = eb[tl], Rc = eb[tr];
    float L_m1 = NEG_INF, R_m1 = NEG_INF;
#pragma unroll
    for (int j = 0; j < 8; j++) {
        float2 Ln = (j < 7) ? eb[(j + 1) * 256 + tl] : make_float2(NEG_INF, NEG_INF);
        float2 Rn = (j < 7) ? eb[(j + 1) * 256 + tr] : make_float2(NEG_INF, NEG_INF);
        float2 pA = pb[j * 256 + t2a];
        float2 pB = pb[j * 256 + t2b];
        {   // k = 2j
            const int k = 2 * j;
            float za = a[k];
            if (k > 0) za = fmaxf(za, a[k - 1]);
            za = fmaxf(za, a[k + 1]);
            float zb = b[k];
            if (k > 0) zb = fmaxf(zb, b[k - 1]);
            zb = fmaxf(zb, b[k + 1]);
            float zi = fmaxf(za, zb);                       // shared inner-x max
            float zl = fmaxf(fmaxf(L_m1, Lc.x), Lc.y);
            float zr = fmaxf(fmaxf(R_m1, Rc.x), Rc.y);
            float mA = lv ? fmaxf(zi, zl) : zi;
            float mB = rv ? fmaxf(zi, zr) : zi;
            float dA = fmaxf(mA, __shfl_up_sync(FULLM, mA, 1, 16));
            dA = fmaxf(dA, __shfl_down_sync(FULLM, mA, 1, 16));
            float dB = fmaxf(mB, __shfl_up_sync(FULLM, mB, 1, 16));
            dB = fmaxf(dB, __shfl_down_sync(FULLM, mB, 1, 16));
            float da = fmaxf(pA.x - dA, 0.0f);
            float db = fmaxf(pB.x - dB, 0.0f);
            if (FIRST) { sA[k] = da; sB[k] = db; }
            else {
                float s = sA[k]; sA[k] = s + fmaxf(da - s * da, 0.0f);
                s = sB[k];       sB[k] = s + fmaxf(db - s * db, 0.0f);
            }
        }
        {   // k = 2j+1
            const int k = 2 * j + 1;
            float za = fmaxf(a[k], a[k - 1]);
            if (k < 15) za = fmaxf(za, a[k + 1]);
            float zb = fmaxf(b[k], b[k - 1]);
            if (k < 15) zb = fmaxf(zb, b[k + 1]);
            float zi = fmaxf(za, zb);
            float zl = fmaxf(fmaxf(Lc.x, Lc.y), Ln.x);
            float zr = fmaxf(fmaxf(Rc.x, Rc.y), Rn.x);
            float mA = lv ? fmaxf(zi, zl) : zi;
            float mB = rv ? fmaxf(zi, zr) : zi;
            float dA = fmaxf(mA, __shfl_up_sync(FULLM, mA, 1, 16));
            dA = fmaxf(dA, __shfl_down_sync(FULLM, mA, 1, 16));
            float dB = fmaxf(mB, __shfl_up_sync(FULLM, mB, 1, 16));
            dB = fmaxf(dB, __shfl_down_sync(FULLM, mB, 1, 16));
            float da = fmaxf(pA.y - dA, 0.0f);
            float db = fmaxf(pB.y - dB, 0.0f);
            if (FIRST) { sA[k] = da; sB[k] = db; }
            else {
                float s = sA[k]; sA[k] = s + fmaxf(da - s * da, 0.0f);
                s = sB[k];       sB[k] = s + fmaxf(db - s * db, 0.0f);
            }
        }
        L_m1 = Lc.y; Lc = Ln;
        R_m1 = Rc.y; Rc = Rn;
    }
}

// ---- packed-bits path: A in bits 0-15, B in bits 16-31 of one word ----

// erode (AND 7-cross, pads=1). Boundary pads injected via OR-masks; the
// cross-half garbage bits from 32-bit shifts land exactly on the pad bits
// and are overridden. Self-clamped y-shfl is identity (e subset of c).
__device__ __forceinline__ unsigned erode_bits_p(unsigned c,
                                                 const unsigned* __restrict__ ib,
                                                 int t, bool lv, bool rv) {
    unsigned e = c & ((c << 1) | 0x00010001u) & ((c >> 1) | 0x80008000u);
    e &= __byte_perm(c, c, 0x1032);                  // inner-x: swap halves
    unsigned L = ib[lv ? t - 16 : t];
    unsigned R = ib[rv ? t + 16 : t];
    if (lv) e &= (L >> 16) | 0xFFFF0000u;            // A &= left thread's B
    if (rv) e &= (R << 16) | 0x0000FFFFu;            // B &= right thread's A
    e &= __shfl_up_sync(FULLM, c, 1, 16) & __shfl_down_sync(FULLM, c, 1, 16);
    return e;
}

// dilate (OR 3x3x3 box, pads=0).
__device__ __forceinline__ unsigned dilate_bits_p(unsigned e,
                                                  const unsigned* __restrict__ ib,
                                                  int t, bool lv, bool rv) {
    unsigned dz = e | ((e << 1) & 0xFFFEFFFEu) | ((e >> 1) & 0x7FFF7FFFu);
    unsigned dx = dz | __byte_perm(dz, dz, 0x1032);  // inner-x
    if (lv) {
        unsigned LB = ib[t - 16] >> 16;
        dx |= (LB | (LB << 1) | (LB >> 1)) & 0xFFFFu;
    }
    if (rv) {
        unsigned RA = ib[t + 16] & 0xFFFFu;
        dx |= ((RA | (RA << 1) | (RA >> 1)) & 0xFFFFu) << 16;
    }
    return dx | __shfl_up_sync(FULLM, dx, 1, 16) | __shfl_down_sync(FULLM, dx, 1, 16);
}

__device__ __forceinline__ double block_tversky(double tp, double fn, double fp) {
    const double s = 1e-8;
    double ab = fp + fn + s;
    double alpha = 0.5 + 0.5 * (fp + s) / ab;
    double beta  = 0.5 + 0.5 * (fn + s) / ab;
    return 1.0 - (tp + s) / (tp + alpha * fp + beta * fn + s);
}

extern __shared__ float2 smem2[];

__global__ void __launch_bounds__(THREADS, 4)
loss_main_kernel(const float* __restrict__ pred, const float* __restrict__ gt,
                 const float* __restrict__ w1, const float* __restrict__ w2,
                 float* __restrict__ out, int nblk) {
    float2* f0 = smem2;
    float2* f1 = smem2 + F2N;
    float2* f2 = smem2 + 2 * F2N;
    unsigned* ib0 = (unsigned*)(smem2 + 3 * F2N);   // 128 packed words
    unsigned* ib1 = ib0 + 128;
    __shared__ float red[4][6];
    __shared__ unsigned last_flag;

    int t = threadIdx.x;
    int blk = blockIdx.x;
    int by = blk % NB;
    int bx = (blk / NB) % NB;
    int bz = (blk / (NB * NB)) % NB;
    int n  = blk / (NB * NB * NB);

    int base = n * DIM * DIM * DIM
             + (bz * 16) * DIM * DIM
             + (bx * 16) * DIM
             + (by * 16);

    int xp = t >> 4;           // x-pair 0..7
    int y  = t & 15;
    int t2a = (xp << 5) + y;   // col 2xp
    int t2b = t2a + 16;        // col 2xp+1
    bool lv = xp > 0, rv = xp < 7;
    int tl = lv ? t2a - 16 : t2a;
    int tr = rv ? t2b + 16 : t2b;
    int ayu = t2a - (y > 0 ? 1 : 0);    // y-1 (self at pad: identity for min)
    int ayd = t2a + (y < 15 ? 1 : 0);   // y+1
    int lane = t & 31, w = t >> 5;

    // ---- load both columns; dice partials banked early ----
    float a[16], b[16];
    unsigned mAB = 0;
    {
        float pg = 0.f, pp = 0.f;
        int giA = base + (2 * xp) * DIM + y;
#pragma unroll
        for (int k = 0; k < 16; k++) {
            float gva = gt[giA];
            float pva = pred[giA];
            float gvb = gt[giA + DIM];
            float pvb = pred[giA + DIM];
            a[k] = pva; b[k] = pvb;
            if (gva != 0.0f) { mAB |= (1u << k); pg += pva; }
            if (gvb != 0.0f) { mAB |= (0x10000u << k); pg += pvb; }
            pp += pva * pva + pvb * pvb;
            giA += DIM * DIM;
        }
        float gg = (float)__popc(mAB);
        float s0 = warp_sum(pg), s1 = warp_sum(pp), s2 = warp_sum(gg);
        if (lane == 0) { red[w][0] = s0; red[w][1] = s1; red[w][2] = s2; }
    }

    // NOTE: reference's boundary conv kernel is -(ones.at[13].set(26)) -- all
    // taps negative -- so (b > 0.1) is identically false, loss_bdr == 0. Dropped.

    float sA[16], sB[16];
    unsigned mcur = mAB, mprev, msk = 0;

    // P0: publish e0; erode -> e1
#pragma unroll
    for (int j = 0; j < 8; j++) {
        f0[j * 256 + t2a] = make_float2(a[2 * j], a[2 * j + 1]);
        f0[j * 256 + t2b] = make_float2(b[2 * j], b[2 * j + 1]);
    }
    ib0[t] = mcur;
    __syncthreads();
    mprev = mcur;
    mcur = erode_bits_p(mcur, ib0, t, lv, rv);
    erode_store(a, b, f0, f1, t2a, t2b, tl, tr, ayu, ayd, lv, rv);

    // P1: dilate(e1; prev=e0) init; erode -> e2
    ib1[t] = mcur;
    __syncthreads();
    dilate_upd<true>(a, b, sA, sB, f1, f0, t2a, t2b, tl, tr, lv, rv);
    msk |= mprev & ~dilate_bits_p(mcur, ib1, t, lv, rv);
    mprev = mcur;
    mcur = erode_bits_p(mcur, ib1, t, lv, rv);
    erode_store(a, b, f1, f2, t2a, t2b, tl, tr, ayu, ayd, lv, rv);

    // P2: dilate(e2; prev=e1); erode -> e3
    ib0[t] = mcur;
    __syncthreads();
    dilate_upd<false>(a, b, sA, sB, f2, f1, t2a, t2b, tl, tr, lv, rv);
    msk |= mprev & ~dilate_bits_p(mcur, ib0, t, lv, rv);
    mprev = mcur;
    mcur = erode_bits_p(mcur, ib0, t, lv, rv);
    erode_store(a, b, f2, f0, t2a, t2b, tl, tr, ayu, ayd, lv, rv);

    // P3: dilate(e3; prev=e2); erode -> e4
    ib1[t] = mcur;
    __syncthreads();
    dilate_upd<false>(a, b, sA, sB, f0, f2, t2a, t2b, tl, tr, lv, rv);
    msk |= mprev & ~dilate_bits_p(mcur, ib1, t, lv, rv);
    mprev = mcur;
    mcur = erode_bits_p(mcur, ib1, t, lv, rv);
    erode_store(a, b, f0, f1, t2a, t2b, tl, tr, ayu, ayd, lv, rv);

    // P4: dilate(e4; prev=e3) -- final update, no erode
    ib0[t] = mcur;
    __syncthreads();
    dilate_upd<false>(a, b, sA, sB, f1, f0, t2a, t2b, tl, tr, lv, rv);
    msk |= mprev & ~dilate_bits_p(mcur, ib0, t, lv, rv);

    // ---- clDice tversky counts ----
    float tpc = 0.f, fnc = 0.f, fpc = 0.f;
#pragma unroll
    for (int k = 0; k < 16; k++) {
        float spa = sA[k];
        if ((msk >> k) & 1u) { tpc += spa; fnc += 1.0f - spa; }
        else { fpc += spa; }
        float spb = sB[k];
        if ((msk >> (k + 16)) & 1u) { tpc += spb; fnc += 1.0f - spb; }
        else { fpc += spb; }
    }
    {
        float s3 = warp_sum(tpc), s4 = warp_sum(fnc), s5 = warp_sum(fpc);
        if (lane == 0) { red[w][3] = s3; red[w][4] = s4; red[w][5] = s5; }
    }
    __syncthreads();

    // ---- per-block accumulate + last-CTA finalize ----
    if (t == 0) {
        double s[6];
#pragma unroll
        for (int i = 0; i < 6; i++) {
            double acc = 0.0;
#pragma unroll
            for (int ww = 0; ww < 4; ww++) acc += (double)red[ww][i];
            s[i] = acc;
        }
        atomicAdd(&g_acc[0], s[0]);
        atomicAdd(&g_acc[1], s[1]);
        atomicAdd(&g_acc[2], s[2]);
        atomicAdd(&g_acc[3], block_tversky(s[3], s[4], s[5]));
        __threadfence();
        unsigned c = atomicAdd(&g_count, 1u);
        last_flag = (c == (unsigned)(nblk - 1)) ? 1u : 0u;
    }
    __syncthreads();

    if (last_flag && t == 0) {
        __threadfence();
        double pg = g_acc[0], pp = g_acc[1], gg = g_acc[2], cl = g_acc[3];
        double dice = 2.0 * pg / fmax(pp + gg, 1e-6);
        double dice_loss = 1.0 - dice;
        double w1s = (double)w1[0], w2s = (double)w2[0];
        double edge = (cl / (w2s * w2s)) / (2.0 * (double)nblk)
                    + log(1.0 + fabs(w1s) * fabs(w2s));
        out[0] = (float)((dice < 0.8) ? dice_loss : dice_loss + edge);
        g_acc[0] = 0.0; g_acc[1] = 0.0; g_acc[2] = 0.0; g_acc[3] = 0.0;
        g_count = 0u;
        __threadfence();
    }
}

extern "C" void kernel_launch(void* const* d_in, const int* in_sizes, int n_in,
                              void* d_out, int out_size) {
    const float* pred = (const float*)d_in[0];
    const float* gt   = (const float*)d_in[1];
    const float* w1   = (const float*)d_in[2];
    const float* w2   = (const float*)d_in[3];
    float* out = (float*)d_out;

    int total = in_sizes[0];
    int N = total / (DIM * DIM * DIM);
    int nblk = N * NB * NB * NB;

    int smem_bytes = 3 * F2N * (int)sizeof(float2) + 256 * (int)sizeof(unsigned);
    cudaFuncSetAttribute(loss_main_kernel,
                         cudaFuncAttributeMaxDynamicSharedMemorySize, smem_bytes);

    loss_main_kernel<<<nblk, THREADS, smem_bytes>>>(pred, gt, w1, w2, out, nblk);
}